// round 10
// baseline (speedup 1.0000x reference)
#include <cuda_runtime.h>
#include <cuda_bf16.h>
#include <math.h>
#include <stdint.h>

// ---------------- problem dims ----------------
#define B_DIM 2
#define S_DIM 2048
#define H_SIZE 2048
#define NK 16
#define NV 32
#define DK 128
#define DV 128
#define KEY_DIM 2048
#define VAL_DIM 4096
#define QKVZ_DIM 12288
#define CONV_DIM 8192
#define BS_TOT (B_DIM * S_DIM)   // 4096
#define EPS 1e-6f

// ---------------- scratch ----------------
__device__ float g_qkvz[(size_t)BS_TOT * QKVZ_DIM];
__device__ float g_ba[(size_t)BS_TOT * 64];
__device__ float g_qn[(size_t)BS_TOT * KEY_DIM];
__device__ float g_kn[(size_t)BS_TOT * KEY_DIM];
__device__ float g_v[(size_t)BS_TOT * VAL_DIM];
__device__ float g_ge[(size_t)BS_TOT * NV];
__device__ float g_beta[(size_t)BS_TOT * NV];
__device__ float g_core[(size_t)BS_TOT * VAL_DIM];

__device__ __nv_bfloat16 g_xhi[(size_t)BS_TOT * H_SIZE];
__device__ __nv_bfloat16 g_xlo[(size_t)BS_TOT * H_SIZE];
__device__ __nv_bfloat16 g_wqhi[(size_t)QKVZ_DIM * H_SIZE];
__device__ __nv_bfloat16 g_wqlo[(size_t)QKVZ_DIM * H_SIZE];
__device__ __nv_bfloat16 g_wohi[(size_t)H_SIZE * VAL_DIM];
__device__ __nv_bfloat16 g_wolo[(size_t)H_SIZE * VAL_DIM];
__device__ __nv_bfloat16 g_chi[(size_t)BS_TOT * VAL_DIM];
__device__ __nv_bfloat16 g_clo[(size_t)BS_TOT * VAL_DIM];

// ---------------- helpers ----------------
__device__ __forceinline__ uint32_t smem_u32(const void* p) {
    uint32_t a;
    asm("{ .reg .u64 t; cvta.to.shared.u64 t, %1; cvt.u32.u64 %0, t; }" : "=r"(a) : "l"(p));
    return a;
}
__device__ __forceinline__ void cp16(uint32_t dst, const void* src) {
    asm volatile("cp.async.cg.shared.global [%0], [%1], 16;" :: "r"(dst), "l"(src) : "memory");
}
template <int N> __device__ __forceinline__ void cp_wait() {
    asm volatile("cp.async.wait_group %0;" :: "n"(N) : "memory");
}
__device__ __forceinline__ void ldmatrix4(uint32_t* r, uint32_t addr) {
    asm volatile("ldmatrix.sync.aligned.m8n8.x4.shared.b16 {%0,%1,%2,%3}, [%4];"
                 : "=r"(r[0]), "=r"(r[1]), "=r"(r[2]), "=r"(r[3]) : "r"(addr));
}
__device__ __forceinline__ void mma16816(float* c, const uint32_t* a, uint32_t b0, uint32_t b1) {
    asm volatile(
        "mma.sync.aligned.m16n8k16.row.col.f32.bf16.bf16.f32 "
        "{%0,%1,%2,%3}, {%4,%5,%6,%7}, {%8,%9}, {%0,%1,%2,%3};"
        : "+f"(c[0]), "+f"(c[1]), "+f"(c[2]), "+f"(c[3])
        : "r"(a[0]), "r"(a[1]), "r"(a[2]), "r"(a[3]), "r"(b0), "r"(b1));
}

// ---------------- fp32 -> bf16 hi/lo split ----------------
__global__ void __launch_bounds__(256) split_kernel(const float4* __restrict__ in,
                                                    __nv_bfloat162* __restrict__ hi,
                                                    __nv_bfloat162* __restrict__ lo,
                                                    int n4) {
    int i = blockIdx.x * 256 + threadIdx.x;
    if (i >= n4) return;
    float4 v = in[i];
    __nv_bfloat16 hx = __float2bfloat16(v.x);
    __nv_bfloat16 hy = __float2bfloat16(v.y);
    __nv_bfloat16 hz = __float2bfloat16(v.z);
    __nv_bfloat16 hw = __float2bfloat16(v.w);
    __nv_bfloat16 lx = __float2bfloat16(v.x - __bfloat162float(hx));
    __nv_bfloat16 ly = __float2bfloat16(v.y - __bfloat162float(hy));
    __nv_bfloat16 lz = __float2bfloat16(v.z - __bfloat162float(hz));
    __nv_bfloat16 lw = __float2bfloat16(v.w - __bfloat162float(hw));
    __nv_bfloat162 a, b, c, d;
    a.x = hx; a.y = hy; b.x = hz; b.y = hw;
    c.x = lx; c.y = ly; d.x = lz; d.y = lw;
    hi[2 * i] = a; hi[2 * i + 1] = b;
    lo[2 * i] = c; lo[2 * i + 1] = d;
}

// ---------------- fused 3-pass mma.sync GEMM ----------------
// Tile 128x256x64, warp tile 64x64, 8 warps (2M x 4N), 2-stage double buffer.
// Per kk-step processed in two N-halves: B fragments 16 regs at a time.
#define MM_BM 128
#define MM_BN 256
#define MM_BK 64
#define MM_A_BYTES 16384
#define MM_B_BYTES 32768
#define MM_STAGE_BYTES (2 * MM_A_BYTES + 2 * MM_B_BYTES)   // 98304
#define MM_SMEM_TOTAL (2 * MM_STAGE_BYTES)                 // 196608

__global__ void __launch_bounds__(256, 1)
gemm_mma(const __nv_bfloat16* __restrict__ Ahi, const __nv_bfloat16* __restrict__ Alo,
         const __nv_bfloat16* __restrict__ Bhi, const __nv_bfloat16* __restrict__ Blo,
         float* __restrict__ C, int M, int N, int K) {
    extern __shared__ char smem[];
    const uint32_t sbase = smem_u32(smem);
    const int tid = threadIdx.x, wid = tid >> 5, lane = tid & 31;
    const int wm = wid & 1;            // 0..1 -> 64 rows
    const int wn = wid >> 1;           // 0..3 -> 64 cols

    const int m0 = blockIdx.y * MM_BM;
    const int n0 = blockIdx.x * MM_BN;
    const int KT = K / MM_BK;

    const int a_lr = lane & 15;
    const uint32_t a_colb = (uint32_t)((lane >> 4) * 16);
    const int b_l = lane & 7, b_q = lane >> 3;
    const uint32_t b_colb = (uint32_t)((b_q & 1) * 16);

    uint32_t arb[4], asw[4], brb[4], bsw[4];
#pragma unroll
    for (int i = 0; i < 4; i++) {
        uint32_t row = (uint32_t)(wm * 64 + a_lr + i * 16);
        arb[i] = row * 128;
        asw[i] = (arb[i] >> 3) & 0x70;
    }
#pragma unroll
    for (int j = 0; j < 4; j++) {
        uint32_t row = (uint32_t)(wn * 64 + (b_q >> 1) * 8 + b_l + j * 16);
        brb[j] = row * 128;
        bsw[j] = (brb[j] >> 3) & 0x70;
    }

    float acc[4][8][4];
#pragma unroll
    for (int i = 0; i < 4; i++)
#pragma unroll
        for (int j = 0; j < 8; j++)
#pragma unroll
            for (int q = 0; q < 4; q++) acc[i][j][q] = 0.f;

    auto load_tile = [&](int kt, int stage) {
        const __nv_bfloat16* Aph = Ahi + (size_t)m0 * K + kt * MM_BK;
        const __nv_bfloat16* Apl = Alo + (size_t)m0 * K + kt * MM_BK;
        const __nv_bfloat16* Bph = Bhi + (size_t)n0 * K + kt * MM_BK;
        const __nv_bfloat16* Bpl = Blo + (size_t)n0 * K + kt * MM_BK;
        uint32_t sS = sbase + stage * MM_STAGE_BYTES;
#pragma unroll
        for (int i = 0; i < 4; i++) {
            int idx = tid + i * 256;
            int row = idx >> 3, u = idx & 7;
            uint32_t off = row * 128 + u * 16;
            off ^= (off >> 3) & 0x70;
            size_t goff = (size_t)row * K + u * 8;
            cp16(sS + off, Aph + goff);
            cp16(sS + MM_A_BYTES + off, Apl + goff);
        }
#pragma unroll
        for (int i = 0; i < 8; i++) {
            int idx = tid + i * 256;
            int row = idx >> 3, u = idx & 7;
            uint32_t off = row * 128 + u * 16;
            off ^= (off >> 3) & 0x70;
            size_t goff = (size_t)row * K + u * 8;
            cp16(sS + 2 * MM_A_BYTES + off, Bph + goff);
            cp16(sS + 2 * MM_A_BYTES + MM_B_BYTES + off, Bpl + goff);
        }
        asm volatile("cp.async.commit_group;" ::: "memory");
    };

    load_tile(0, 0);
    for (int t = 0; t < KT; t++) {
        cp_wait<0>();
        __syncthreads();
        if (t + 1 < KT) load_tile(t + 1, (t + 1) & 1);

        uint32_t sS = sbase + (t & 1) * MM_STAGE_BYTES;
        uint32_t sB = sS + 2 * MM_A_BYTES;
#pragma unroll
        for (int kk = 0; kk < 4; kk++) {
            uint32_t kc = (uint32_t)(kk * 32);
            uint32_t ah[4][4], al[4][4];
#pragma unroll
            for (int i = 0; i < 4; i++) {
                uint32_t ad = sS + arb[i] + ((kc + a_colb) ^ asw[i]);
                ldmatrix4(ah[i], ad);
                ldmatrix4(al[i], ad + MM_A_BYTES);
            }
#pragma unroll
            for (int h = 0; h < 2; h++) {           // N-halves: frags 16 regs
                uint32_t bh[2][4], bl[2][4];
#pragma unroll
                for (int jj = 0; jj < 2; jj++) {
                    int j = 2 * h + jj;
                    uint32_t bd = sB + brb[j] + ((kc + b_colb) ^ bsw[j]);
                    ldmatrix4(bh[jj], bd);
                    ldmatrix4(bl[jj], bd + MM_B_BYTES);
                }
                // sweep 1: hi*hi (16 independent MMAs)
#pragma unroll
                for (int i = 0; i < 4; i++)
#pragma unroll
                    for (int jj = 0; jj < 2; jj++) {
                        int j = 2 * h + jj;
                        mma16816(acc[i][2 * j],     ah[i], bh[jj][0], bh[jj][1]);
                        mma16816(acc[i][2 * j + 1], ah[i], bh[jj][2], bh[jj][3]);
                    }
                // sweep 2: lo*hi
#pragma unroll
                for (int i = 0; i < 4; i++)
#pragma unroll
                    for (int jj = 0; jj < 2; jj++) {
                        int j = 2 * h + jj;
                        mma16816(acc[i][2 * j],     al[i], bh[jj][0], bh[jj][1]);
                        mma16816(acc[i][2 * j + 1], al[i], bh[jj][2], bh[jj][3]);
                    }
                // sweep 3: hi*lo
#pragma unroll
                for (int i = 0; i < 4; i++)
#pragma unroll
                    for (int jj = 0; jj < 2; jj++) {
                        int j = 2 * h + jj;
                        mma16816(acc[i][2 * j],     ah[i], bl[jj][0], bl[jj][1]);
                        mma16816(acc[i][2 * j + 1], ah[i], bl[jj][2], bl[jj][3]);
                    }
            }
        }
    }

    const int row0 = m0 + wm * 64 + (lane >> 2);
    const int col0 = n0 + wn * 64 + (lane & 3) * 2;
#pragma unroll
    for (int i = 0; i < 4; i++)
#pragma unroll
        for (int j = 0; j < 8; j++) {
            int r = row0 + i * 16;
            int c = col0 + j * 8;
            *(float2*)&C[(size_t)r * N + c] = make_float2(acc[i][j][0], acc[i][j][1]);
            *(float2*)&C[(size_t)(r + 8) * N + c] = make_float2(acc[i][j][2], acc[i][j][3]);
        }
}

// ---------------- zero kernel ----------------
__global__ void __launch_bounds__(256) zero_kernel(float4* p) {
    p[blockIdx.x * 256 + threadIdx.x] = make_float4(0.f, 0.f, 0.f, 0.f);
}

// ---------------- split-K SIMT GEMM for ba (N=64) ----------------
#define BA_KSLICE 256
__global__ void __launch_bounds__(256) gemm_ba(const float* __restrict__ A,
                                               const float* __restrict__ B,
                                               float* __restrict__ C,
                                               int M, int N, int K) {
    __shared__ float As[8][128];
    __shared__ float Bs[8][64];
    const int tid = threadIdx.x;
    const int m0 = blockIdx.y * 128;
    const int k_base = blockIdx.z * BA_KSLICE;
    const int lr = tid >> 1;
    const int lk = (tid & 1) * 4;
    const int tx = tid & 15;
    const int ty = tid >> 4;
    const float* Aptr = A + (size_t)(m0 + lr) * K + k_base + lk;
    const float* Bptr = B + (size_t)lr * K + k_base + lk;
    const bool bvalid = lr < 64;

    float acc[8][4];
#pragma unroll
    for (int i = 0; i < 8; i++)
#pragma unroll
        for (int j = 0; j < 4; j++) acc[i][j] = 0.f;

    for (int k0 = 0; k0 < BA_KSLICE; k0 += 8) {
        float4 av = *(const float4*)Aptr;
        float4 bv = bvalid ? *(const float4*)Bptr : make_float4(0.f, 0.f, 0.f, 0.f);
        Aptr += 8; Bptr += 8;
        __syncthreads();
        As[lk + 0][lr] = av.x; As[lk + 1][lr] = av.y;
        As[lk + 2][lr] = av.z; As[lk + 3][lr] = av.w;
        if (bvalid) {
            Bs[lk + 0][lr] = bv.x; Bs[lk + 1][lr] = bv.y;
            Bs[lk + 2][lr] = bv.z; Bs[lk + 3][lr] = bv.w;
        }
        __syncthreads();
#pragma unroll
        for (int kk = 0; kk < 8; kk++) {
            float a[8], b[4];
            float4 a0 = *(const float4*)&As[kk][ty * 4];
            float4 a1 = *(const float4*)&As[kk][ty * 4 + 64];
            a[0]=a0.x; a[1]=a0.y; a[2]=a0.z; a[3]=a0.w;
            a[4]=a1.x; a[5]=a1.y; a[6]=a1.z; a[7]=a1.w;
            float4 bcol = *(const float4*)&Bs[kk][tx * 4];
            b[0]=bcol.x; b[1]=bcol.y; b[2]=bcol.z; b[3]=bcol.w;
#pragma unroll
            for (int i = 0; i < 8; i++)
#pragma unroll
                for (int j = 0; j < 4; j++) acc[i][j] += a[i] * b[j];
        }
    }
#pragma unroll
    for (int i = 0; i < 8; i++) {
        int m = m0 + ty * 4 + (i & 3) + ((i >> 2) * 64);
#pragma unroll
        for (int j = 0; j < 4; j++) {
            int n = tx * 4 + j;
            atomicAdd(&C[(size_t)m * N + n], acc[i][j]);
        }
    }
}

// ---------------- conv + silu + l2norm + gate precompute ----------------
__global__ void __launch_bounds__(256) conv_gate_kernel(
    const float* __restrict__ conv_w, const float* __restrict__ dt_bias,
    const float* __restrict__ A_log) {
    const int bs = blockIdx.x;
    const int s  = bs & (S_DIM - 1);
    const int tid = threadIdx.x;
    __shared__ float buf[CONV_DIM];
    __shared__ float sc[32];
    const float* base = g_qkvz + (size_t)bs * QKVZ_DIM;
    for (int c = tid; c < CONV_DIM; c += 256) {
        float4 w = *(const float4*)&conv_w[c * 4];
        float acc = base[c] * w.w;
        if (s >= 1) acc += g_qkvz[(size_t)(bs - 1) * QKVZ_DIM + c] * w.z;
        if (s >= 2) acc += g_qkvz[(size_t)(bs - 2) * QKVZ_DIM + c] * w.y;
        if (s >= 3) acc += g_qkvz[(size_t)(bs - 3) * QKVZ_DIM + c] * w.x;
        float sg = 1.f / (1.f + __expf(-acc));
        buf[c] = acc * sg;
    }
    __syncthreads();
    const int warp = tid >> 5, lane = tid & 31;
    for (int hh = warp * 4; hh < warp * 4 + 4; hh++) {
        float sum = 0.f;
#pragma unroll
        for (int i = 0; i < 4; i++) {
            float x = buf[hh * 128 + lane + i * 32];
            sum += x * x;
        }
#pragma unroll
        for (int o = 16; o; o >>= 1) sum += __shfl_xor_sync(0xffffffffu, sum, o);
        if (lane == 0) sc[hh] = rsqrtf(sum + EPS);
    }
    __syncthreads();
    float* qnrow = g_qn + (size_t)bs * KEY_DIM;
    float* knrow = g_kn + (size_t)bs * KEY_DIM;
    float* vrow  = g_v  + (size_t)bs * VAL_DIM;
    for (int c = tid; c < KEY_DIM; c += 256) qnrow[c] = buf[c] * sc[c >> 7];
    for (int c = tid; c < KEY_DIM; c += 256) knrow[c] = buf[KEY_DIM + c] * sc[16 + (c >> 7)];
    for (int c = tid; c < VAL_DIM; c += 256) vrow[c] = buf[2 * KEY_DIM + c];
    if (tid < NV) {
        float bb = g_ba[(size_t)bs * 64 + tid];
        float aa = g_ba[(size_t)bs * 64 + NV + tid];
        float be = 1.f / (1.f + expf(-bb));
        float x = aa + dt_bias[tid];
        float sp = (x > 20.f) ? x : log1pf(expf(x));
        float g = -expf(A_log[tid]) * sp;
        g_ge[(size_t)bs * NV + tid] = expf(g);
        g_beta[(size_t)bs * NV + tid] = be;
    }
}

// ---------------- sequential delta-rule scan ----------------
// grid (64, 4): 32 cols/CTA, 8 threads/col (kg = lane&7, 16 k-elems each).
__global__ void __launch_bounds__(256) scan_kernel() {
    const int bh = blockIdx.x;
    const int b = bh >> 5, h = bh & 31;
    const int hk = h >> 1;
    const int tid = threadIdx.x;
    const int warp = tid >> 5, lane = tid & 31;
    const int kg = lane & 7;
    const int col = blockIdx.y * 32 + warp * 4 + (lane >> 3);

    __shared__ __align__(16) float shk[2][128];
    __shared__ __align__(16) float shq[2][128];

    float st[16];
#pragma unroll
    for (int i = 0; i < 16; i++) st[i] = 0.f;

    int bs = b << 11;
    float pk;
    if (tid < 128) pk = g_kn[((size_t)bs * NK + hk) * DK + tid];
    else           pk = g_qn[((size_t)bs * NK + hk) * DK + (tid - 128)];
    float gv = g_ge[(size_t)bs * NV + h];
    float bv = g_beta[(size_t)bs * NV + h];
    float vv = g_v[((size_t)bs * NV + h) * DV + col];

    if (tid < 128) shk[0][tid] = pk;
    else           shq[0][tid - 128] = pk;
    __syncthreads();

    for (int s = 0; s < S_DIM; s++) {
        const int p = s & 1;
        float nk = 0.f, ng = 0.f, nb = 0.f, nv = 0.f;
        if (s + 1 < S_DIM) {
            int bs2 = (b << 11) + s + 1;
            if (tid < 128) nk = g_kn[((size_t)bs2 * NK + hk) * DK + tid];
            else           nk = g_qn[((size_t)bs2 * NK + hk) * DK + (tid - 128)];
            ng = g_ge[(size_t)bs2 * NV + h];
            nb = g_beta[(size_t)bs2 * NV + h];
            nv = g_v[((size_t)bs2 * NV + h) * DV + col];
        }

        const float4* k4 = (const float4*)shk[p];
        const float4* q4 = (const float4*)shq[p];

        float4 kv[4];
        float p0 = 0.f, p1 = 0.f, p2 = 0.f, p3 = 0.f;
#pragma unroll
        for (int j = 0; j < 4; j++) {
            kv[j] = k4[kg * 4 + j];
            p0 += kv[j].x * st[4 * j + 0];
            p1 += kv[j].y * st[4 * j + 1];
            p2 += kv[j].z * st[4 * j + 2];
            p3 += kv[j].w * st[4 * j + 3];
        }
        float part = (p0 + p1) + (p2 + p3);
        part += __shfl_xor_sync(0xffffffffu, part, 1);
        part += __shfl_xor_sync(0xffffffffu, part, 2);
        part += __shfl_xor_sync(0xffffffffu, part, 4);

        float delta = bv * (vv - gv * part);

        float o0 = 0.f, o1 = 0.f, o2 = 0.f, o3 = 0.f;
#pragma unroll
        for (int j = 0; j < 4; j++) {
            float4 qv = q4[kg * 4 + j];
            float s0 = st[4 * j + 0] * gv + kv[j].x * delta;
            float s1 = st[4 * j + 1] * gv + kv[j].y * delta;
            float s2 = st[4 * j + 2] * gv + kv[j].z * delta;
            float s3 = st[4 * j + 3] * gv + kv[j].w * delta;
            st[4 * j + 0] = s0; st[4 * j + 1] = s1;
            st[4 * j + 2] = s2; st[4 * j + 3] = s3;
            o0 += qv.x * s0; o1 += qv.y * s1;
            o2 += qv.z * s2; o3 += qv.w * s3;
        }
        float o = (o0 + o1) + (o2 + o3);
        o += __shfl_xor_sync(0xffffffffu, o, 1);
        o += __shfl_xor_sync(0xffffffffu, o, 2);
        o += __shfl_xor_sync(0xffffffffu, o, 4);

        if (kg == 0) {
            int bsc = (b << 11) + s;
            g_core[((size_t)bsc * NV + h) * DV + col] = o;
        }

        if (s + 1 < S_DIM) {
            if (tid < 128) shk[p ^ 1][tid] = nk;
            else           shq[p ^ 1][tid - 128] = nk;
        }
        __syncthreads();
        gv = ng; bv = nb; vv = nv;
    }
}

// ---------------- RMSNorm + silu(z) gate -> bf16 hi/lo directly ------------
__global__ void __launch_bounds__(256) rmsgate_kernel(const float* __restrict__ norm_w) {
    const int r = blockIdx.x;
    const int tid = threadIdx.x;
    const float* row = g_core + (size_t)r * VAL_DIM;
    __shared__ float red[8];
    float ss = 0.f;
    for (int i = tid; i < VAL_DIM; i += 256) {
        float x = row[i];
        ss += x * x;
    }
#pragma unroll
    for (int o = 16; o; o >>= 1) ss += __shfl_xor_sync(0xffffffffu, ss, o);
    if ((tid & 31) == 0) red[tid >> 5] = ss;
    __syncthreads();
    if (tid == 0) {
        float tot = 0.f;
#pragma unroll
        for (int i = 0; i < 8; i++) tot += red[i];
        red[0] = rsqrtf(tot / (float)VAL_DIM + EPS);
    }
    __syncthreads();
    const float scale = red[0];
    const float* zrow = g_qkvz + (size_t)r * QKVZ_DIM + (2 * KEY_DIM + VAL_DIM);
    __nv_bfloat16* hrow = g_chi + (size_t)r * VAL_DIM;
    __nv_bfloat16* lrow = g_clo + (size_t)r * VAL_DIM;
    for (int i = tid; i < VAL_DIM; i += 256) {
        float zv = zrow[i];
        float sil = zv / (1.f + __expf(-zv));
        float val = row[i] * scale * (1.f + norm_w[i]) * sil;
        __nv_bfloat16 hv = __float2bfloat16(val);
        hrow[i] = hv;
        lrow[i] = __float2bfloat16(val - __bfloat162float(hv));
    }
}

// ---------------- launch ----------------
extern "C" void kernel_launch(void* const* d_in, const int* in_sizes, int n_in,
                              void* d_out, int out_size) {
    const float* x       = (const float*)d_in[0];
    const float* W_qkvz  = (const float*)d_in[1];
    const float* W_ba    = (const float*)d_in[2];
    const float* conv_w  = (const float*)d_in[3];
    const float* dt_bias = (const float*)d_in[4];
    const float* A_log   = (const float*)d_in[5];
    const float* norm_w  = (const float*)d_in[6];
    const float* W_out   = (const float*)d_in[7];
    float* out = (float*)d_out;

    float *p_qkvz, *p_ba;
    cudaGetSymbolAddress((void**)&p_qkvz, g_qkvz);
    cudaGetSymbolAddress((void**)&p_ba, g_ba);
    __nv_bfloat16 *p_xhi, *p_xlo, *p_wqhi, *p_wqlo, *p_wohi, *p_wolo, *p_chi, *p_clo;
    cudaGetSymbolAddress((void**)&p_xhi, g_xhi);
    cudaGetSymbolAddress((void**)&p_xlo, g_xlo);
    cudaGetSymbolAddress((void**)&p_wqhi, g_wqhi);
    cudaGetSymbolAddress((void**)&p_wqlo, g_wqlo);
    cudaGetSymbolAddress((void**)&p_wohi, g_wohi);
    cudaGetSymbolAddress((void**)&p_wolo, g_wolo);
    cudaGetSymbolAddress((void**)&p_chi, g_chi);
    cudaGetSymbolAddress((void**)&p_clo, g_clo);

    cudaFuncSetAttribute(gemm_mma, cudaFuncAttributeMaxDynamicSharedMemorySize, MM_SMEM_TOTAL);

    {
        int n4 = (BS_TOT * H_SIZE) / 4;
        split_kernel<<<(n4 + 255) / 256, 256>>>((const float4*)x,
                                                (__nv_bfloat162*)p_xhi, (__nv_bfloat162*)p_xlo, n4);
    }
    {
        int n4 = (QKVZ_DIM * H_SIZE) / 4;
        split_kernel<<<(n4 + 255) / 256, 256>>>((const float4*)W_qkvz,
                                                (__nv_bfloat162*)p_wqhi, (__nv_bfloat162*)p_wqlo, n4);
    }
    {
        int n4 = (H_SIZE * VAL_DIM) / 4;
        split_kernel<<<(n4 + 255) / 256, 256>>>((const float4*)W_out,
                                                (__nv_bfloat162*)p_wohi, (__nv_bfloat162*)p_wolo, n4);
    }
    gemm_mma<<<dim3(QKVZ_DIM / MM_BN, BS_TOT / MM_BM), 256, MM_SMEM_TOTAL>>>(
        p_xhi, p_xlo, p_wqhi, p_wqlo, p_qkvz, BS_TOT, QKVZ_DIM, H_SIZE);
    zero_kernel<<<(BS_TOT * 64) / (256 * 4), 256>>>((float4*)p_ba);
    gemm_ba<<<dim3(1, BS_TOT / 128, H_SIZE / BA_KSLICE), 256>>>(x, W_ba, p_ba,
                                                                BS_TOT, 64, H_SIZE);
    conv_gate_kernel<<<BS_TOT, 256>>>(conv_w, dt_bias, A_log);
    scan_kernel<<<dim3(64, 4), 256>>>();
    rmsgate_kernel<<<BS_TOT, 256>>>(norm_w);
    gemm_mma<<<dim3(H_SIZE / MM_BN, BS_TOT / MM_BM), 256, MM_SMEM_TOTAL>>>(
        p_chi, p_clo, p_wohi, p_wolo, out, BS_TOT, H_SIZE, VAL_DIM);
}

// round 11
// speedup vs baseline: 1.0298x; 1.0298x over previous
#include <cuda_runtime.h>
#include <cuda_bf16.h>
#include <math.h>
#include <stdint.h>

// ---------------- problem dims ----------------
#define B_DIM 2
#define S_DIM 2048
#define H_SIZE 2048
#define NK 16
#define NV 32
#define DK 128
#define DV 128
#define KEY_DIM 2048
#define VAL_DIM 4096
#define QKVZ_DIM 12288
#define CONV_DIM 8192
#define BS_TOT (B_DIM * S_DIM)   // 4096
#define EPS 1e-6f

// ---------------- scratch ----------------
__device__ float g_qkvz[(size_t)BS_TOT * QKVZ_DIM];
__device__ float g_ba[(size_t)BS_TOT * 64];
__device__ float g_qn[(size_t)BS_TOT * KEY_DIM];
__device__ float g_kn[(size_t)BS_TOT * KEY_DIM];
__device__ float g_v[(size_t)BS_TOT * VAL_DIM];
__device__ float g_ge[(size_t)BS_TOT * NV];
__device__ float g_beta[(size_t)BS_TOT * NV];
__device__ float g_core[(size_t)BS_TOT * VAL_DIM];

__device__ __nv_bfloat16 g_xhi[(size_t)BS_TOT * H_SIZE];
__device__ __nv_bfloat16 g_xlo[(size_t)BS_TOT * H_SIZE];
__device__ __nv_bfloat16 g_wqhi[(size_t)QKVZ_DIM * H_SIZE];
__device__ __nv_bfloat16 g_wqlo[(size_t)QKVZ_DIM * H_SIZE];
__device__ __nv_bfloat16 g_wohi[(size_t)H_SIZE * VAL_DIM];
__device__ __nv_bfloat16 g_wolo[(size_t)H_SIZE * VAL_DIM];
__device__ __nv_bfloat16 g_chi[(size_t)BS_TOT * VAL_DIM];
__device__ __nv_bfloat16 g_clo[(size_t)BS_TOT * VAL_DIM];

// ---------------- helpers ----------------
__device__ __forceinline__ uint32_t smem_u32(const void* p) {
    uint32_t a;
    asm("{ .reg .u64 t; cvta.to.shared.u64 t, %1; cvt.u32.u64 %0, t; }" : "=r"(a) : "l"(p));
    return a;
}
__device__ __forceinline__ void cp16(uint32_t dst, const void* src) {
    asm volatile("cp.async.cg.shared.global [%0], [%1], 16;" :: "r"(dst), "l"(src) : "memory");
}
template <int N> __device__ __forceinline__ void cp_wait() {
    asm volatile("cp.async.wait_group %0;" :: "n"(N) : "memory");
}
__device__ __forceinline__ void ldmatrix4(uint32_t* r, uint32_t addr) {
    asm volatile("ldmatrix.sync.aligned.m8n8.x4.shared.b16 {%0,%1,%2,%3}, [%4];"
                 : "=r"(r[0]), "=r"(r[1]), "=r"(r[2]), "=r"(r[3]) : "r"(addr));
}
__device__ __forceinline__ void mma16816(float* c, const uint32_t* a, uint32_t b0, uint32_t b1) {
    asm volatile(
        "mma.sync.aligned.m16n8k16.row.col.f32.bf16.bf16.f32 "
        "{%0,%1,%2,%3}, {%4,%5,%6,%7}, {%8,%9}, {%0,%1,%2,%3};"
        : "+f"(c[0]), "+f"(c[1]), "+f"(c[2]), "+f"(c[3])
        : "r"(a[0]), "r"(a[1]), "r"(a[2]), "r"(a[3]), "r"(b0), "r"(b1));
}

// ---------------- fp32 -> bf16 hi/lo split ----------------
__global__ void __launch_bounds__(256) split_kernel(const float4* __restrict__ in,
                                                    __nv_bfloat162* __restrict__ hi,
                                                    __nv_bfloat162* __restrict__ lo,
                                                    int n4) {
    int i = blockIdx.x * 256 + threadIdx.x;
    if (i >= n4) return;
    float4 v = in[i];
    __nv_bfloat16 hx = __float2bfloat16(v.x);
    __nv_bfloat16 hy = __float2bfloat16(v.y);
    __nv_bfloat16 hz = __float2bfloat16(v.z);
    __nv_bfloat16 hw = __float2bfloat16(v.w);
    __nv_bfloat16 lx = __float2bfloat16(v.x - __bfloat162float(hx));
    __nv_bfloat16 ly = __float2bfloat16(v.y - __bfloat162float(hy));
    __nv_bfloat16 lz = __float2bfloat16(v.z - __bfloat162float(hz));
    __nv_bfloat16 lw = __float2bfloat16(v.w - __bfloat162float(hw));
    __nv_bfloat162 a, b, c, d;
    a.x = hx; a.y = hy; b.x = hz; b.y = hw;
    c.x = lx; c.y = ly; d.x = lz; d.y = lw;
    hi[2 * i] = a; hi[2 * i + 1] = b;
    lo[2 * i] = c; lo[2 * i + 1] = d;
}

// ---------------- fused 3-pass mma.sync GEMM, 2 CTAs/SM ----------------
// Tile 128x128x64, warp tile 64x32, 8 warps (2M x 4N), SINGLE stage (64KB).
// 2 CTAs per SM: each CTA's load/barrier phases are covered by the sibling
// CTA's MMA stream (cross-CTA latency hiding instead of intra-CTA stages).
#define MM_BM 128
#define MM_BN 128
#define MM_BK 64
#define MM_TILE_BYTES 16384
#define MM_SMEM_TOTAL (4 * MM_TILE_BYTES)   // 65536: [Ahi][Alo][Bhi][Blo]

__global__ void __launch_bounds__(256, 2)
gemm_mma(const __nv_bfloat16* __restrict__ Ahi, const __nv_bfloat16* __restrict__ Alo,
         const __nv_bfloat16* __restrict__ Bhi, const __nv_bfloat16* __restrict__ Blo,
         float* __restrict__ C, int M, int N, int K) {
    extern __shared__ char smem[];
    const uint32_t sbase = smem_u32(smem);
    const int tid = threadIdx.x, wid = tid >> 5, lane = tid & 31;
    const int wm = wid & 1;            // 0..1 -> 64 rows
    const int wn = wid >> 1;           // 0..3 -> 32 cols

    const int m0 = blockIdx.y * MM_BM;
    const int n0 = blockIdx.x * MM_BN;
    const int KT = K / MM_BK;

    const int a_lr = lane & 15;
    const uint32_t a_colb = (uint32_t)((lane >> 4) * 16);
    const int b_l = lane & 7, b_q = lane >> 3;
    const uint32_t b_colb = (uint32_t)((b_q & 1) * 16);

    uint32_t arb[4], asw[4], brb[2], bsw[2];
#pragma unroll
    for (int i = 0; i < 4; i++) {
        uint32_t row = (uint32_t)(wm * 64 + a_lr + i * 16);
        arb[i] = row * 128;
        asw[i] = (arb[i] >> 3) & 0x70;
    }
#pragma unroll
    for (int j = 0; j < 2; j++) {
        uint32_t row = (uint32_t)(wn * 32 + (b_q >> 1) * 8 + b_l + j * 16);
        brb[j] = row * 128;
        bsw[j] = (brb[j] >> 3) & 0x70;
    }

    float acc[4][4][4];
#pragma unroll
    for (int i = 0; i < 4; i++)
#pragma unroll
        for (int j = 0; j < 4; j++)
#pragma unroll
            for (int q = 0; q < 4; q++) acc[i][j][q] = 0.f;

    for (int t = 0; t < KT; t++) {
        // ---- load tile t into the single stage ----
        {
            const __nv_bfloat16* Aph = Ahi + (size_t)m0 * K + t * MM_BK;
            const __nv_bfloat16* Apl = Alo + (size_t)m0 * K + t * MM_BK;
            const __nv_bfloat16* Bph = Bhi + (size_t)n0 * K + t * MM_BK;
            const __nv_bfloat16* Bpl = Blo + (size_t)n0 * K + t * MM_BK;
#pragma unroll
            for (int i = 0; i < 4; i++) {
                int idx = tid + i * 256;           // 1024 chunks per tile
                int row = idx >> 3, u = idx & 7;
                uint32_t off = row * 128 + u * 16;
                off ^= (off >> 3) & 0x70;
                size_t goff = (size_t)row * K + u * 8;
                cp16(sbase + off, Aph + goff);
                cp16(sbase + MM_TILE_BYTES + off, Apl + goff);
                cp16(sbase + 2 * MM_TILE_BYTES + off, Bph + goff);
                cp16(sbase + 3 * MM_TILE_BYTES + off, Bpl + goff);
            }
            asm volatile("cp.async.commit_group;" ::: "memory");
        }
        cp_wait<0>();
        __syncthreads();

        uint32_t sB = sbase + 2 * MM_TILE_BYTES;
#pragma unroll
        for (int kk = 0; kk < 4; kk++) {
            uint32_t kc = (uint32_t)(kk * 32);
            uint32_t bh[2][4], bl[2][4];
#pragma unroll
            for (int j = 0; j < 2; j++) {
                uint32_t bd = sB + brb[j] + ((kc + b_colb) ^ bsw[j]);
                ldmatrix4(bh[j], bd);
                ldmatrix4(bl[j], bd + MM_TILE_BYTES);
            }
#pragma unroll
            for (int ih = 0; ih < 2; ih++) {
                uint32_t ah[2][4], al[2][4];
#pragma unroll
                for (int i2 = 0; i2 < 2; i2++) {
                    int i = ih * 2 + i2;
                    uint32_t ad = sbase + arb[i] + ((kc + a_colb) ^ asw[i]);
                    ldmatrix4(ah[i2], ad);
                    ldmatrix4(al[i2], ad + MM_TILE_BYTES);
                }
                // sweep 1: hi*hi (8 independent MMAs)
#pragma unroll
                for (int i2 = 0; i2 < 2; i2++)
#pragma unroll
                    for (int j = 0; j < 2; j++) {
                        int i = ih * 2 + i2;
                        mma16816(acc[i][2 * j],     ah[i2], bh[j][0], bh[j][1]);
                        mma16816(acc[i][2 * j + 1], ah[i2], bh[j][2], bh[j][3]);
                    }
                // sweep 2: lo*hi
#pragma unroll
                for (int i2 = 0; i2 < 2; i2++)
#pragma unroll
                    for (int j = 0; j < 2; j++) {
                        int i = ih * 2 + i2;
                        mma16816(acc[i][2 * j],     al[i2], bh[j][0], bh[j][1]);
                        mma16816(acc[i][2 * j + 1], al[i2], bh[j][2], bh[j][3]);
                    }
                // sweep 3: hi*lo
#pragma unroll
                for (int i2 = 0; i2 < 2; i2++)
#pragma unroll
                    for (int j = 0; j < 2; j++) {
                        int i = ih * 2 + i2;
                        mma16816(acc[i][2 * j],     ah[i2], bl[j][0], bl[j][1]);
                        mma16816(acc[i][2 * j + 1], ah[i2], bl[j][2], bl[j][3]);
                    }
            }
        }
        __syncthreads();   // WAR: smem reuse next iteration
    }

    const int row0 = m0 + wm * 64 + (lane >> 2);
    const int col0 = n0 + wn * 32 + (lane & 3) * 2;
#pragma unroll
    for (int i = 0; i < 4; i++)
#pragma unroll
        for (int j = 0; j < 4; j++) {
            int r = row0 + i * 16;
            int c = col0 + j * 8;
            *(float2*)&C[(size_t)r * N + c] = make_float2(acc[i][j][0], acc[i][j][1]);
            *(float2*)&C[(size_t)(r + 8) * N + c] = make_float2(acc[i][j][2], acc[i][j][3]);
        }
}

// ---------------- zero kernel ----------------
__global__ void __launch_bounds__(256) zero_kernel(float4* p) {
    p[blockIdx.x * 256 + threadIdx.x] = make_float4(0.f, 0.f, 0.f, 0.f);
}

// ---------------- split-K SIMT GEMM for ba (N=64) ----------------
#define BA_KSLICE 256
__global__ void __launch_bounds__(256) gemm_ba(const float* __restrict__ A,
                                               const float* __restrict__ B,
                                               float* __restrict__ C,
                                               int M, int N, int K) {
    __shared__ float As[8][128];
    __shared__ float Bs[8][64];
    const int tid = threadIdx.x;
    const int m0 = blockIdx.y * 128;
    const int k_base = blockIdx.z * BA_KSLICE;
    const int lr = tid >> 1;
    const int lk = (tid & 1) * 4;
    const int tx = tid & 15;
    const int ty = tid >> 4;
    const float* Aptr = A + (size_t)(m0 + lr) * K + k_base + lk;
    const float* Bptr = B + (size_t)lr * K + k_base + lk;
    const bool bvalid = lr < 64;

    float acc[8][4];
#pragma unroll
    for (int i = 0; i < 8; i++)
#pragma unroll
        for (int j = 0; j < 4; j++) acc[i][j] = 0.f;

    for (int k0 = 0; k0 < BA_KSLICE; k0 += 8) {
        float4 av = *(const float4*)Aptr;
        float4 bv = bvalid ? *(const float4*)Bptr : make_float4(0.f, 0.f, 0.f, 0.f);
        Aptr += 8; Bptr += 8;
        __syncthreads();
        As[lk + 0][lr] = av.x; As[lk + 1][lr] = av.y;
        As[lk + 2][lr] = av.z; As[lk + 3][lr] = av.w;
        if (bvalid) {
            Bs[lk + 0][lr] = bv.x; Bs[lk + 1][lr] = bv.y;
            Bs[lk + 2][lr] = bv.z; Bs[lk + 3][lr] = bv.w;
        }
        __syncthreads();
#pragma unroll
        for (int kk = 0; kk < 8; kk++) {
            float a[8], b[4];
            float4 a0 = *(const float4*)&As[kk][ty * 4];
            float4 a1 = *(const float4*)&As[kk][ty * 4 + 64];
            a[0]=a0.x; a[1]=a0.y; a[2]=a0.z; a[3]=a0.w;
            a[4]=a1.x; a[5]=a1.y; a[6]=a1.z; a[7]=a1.w;
            float4 bcol = *(const float4*)&Bs[kk][tx * 4];
            b[0]=bcol.x; b[1]=bcol.y; b[2]=bcol.z; b[3]=bcol.w;
#pragma unroll
            for (int i = 0; i < 8; i++)
#pragma unroll
                for (int j = 0; j < 4; j++) acc[i][j] += a[i] * b[j];
        }
    }
#pragma unroll
    for (int i = 0; i < 8; i++) {
        int m = m0 + ty * 4 + (i & 3) + ((i >> 2) * 64);
#pragma unroll
        for (int j = 0; j < 4; j++) {
            int n = tx * 4 + j;
            atomicAdd(&C[(size_t)m * N + n], acc[i][j]);
        }
    }
}

// ---------------- conv + silu + l2norm + gate precompute ----------------
__global__ void __launch_bounds__(256) conv_gate_kernel(
    const float* __restrict__ conv_w, const float* __restrict__ dt_bias,
    const float* __restrict__ A_log) {
    const int bs = blockIdx.x;
    const int s  = bs & (S_DIM - 1);
    const int tid = threadIdx.x;
    __shared__ float buf[CONV_DIM];
    __shared__ float sc[32];
    const float* base = g_qkvz + (size_t)bs * QKVZ_DIM;
    for (int c = tid; c < CONV_DIM; c += 256) {
        float4 w = *(const float4*)&conv_w[c * 4];
        float acc = base[c] * w.w;
        if (s >= 1) acc += g_qkvz[(size_t)(bs - 1) * QKVZ_DIM + c] * w.z;
        if (s >= 2) acc += g_qkvz[(size_t)(bs - 2) * QKVZ_DIM + c] * w.y;
        if (s >= 3) acc += g_qkvz[(size_t)(bs - 3) * QKVZ_DIM + c] * w.x;
        float sg = 1.f / (1.f + __expf(-acc));
        buf[c] = acc * sg;
    }
    __syncthreads();
    const int warp = tid >> 5, lane = tid & 31;
    for (int hh = warp * 4; hh < warp * 4 + 4; hh++) {
        float sum = 0.f;
#pragma unroll
        for (int i = 0; i < 4; i++) {
            float x = buf[hh * 128 + lane + i * 32];
            sum += x * x;
        }
#pragma unroll
        for (int o = 16; o; o >>= 1) sum += __shfl_xor_sync(0xffffffffu, sum, o);
        if (lane == 0) sc[hh] = rsqrtf(sum + EPS);
    }
    __syncthreads();
    float* qnrow = g_qn + (size_t)bs * KEY_DIM;
    float* knrow = g_kn + (size_t)bs * KEY_DIM;
    float* vrow  = g_v  + (size_t)bs * VAL_DIM;
    for (int c = tid; c < KEY_DIM; c += 256) qnrow[c] = buf[c] * sc[c >> 7];
    for (int c = tid; c < KEY_DIM; c += 256) knrow[c] = buf[KEY_DIM + c] * sc[16 + (c >> 7)];
    for (int c = tid; c < VAL_DIM; c += 256) vrow[c] = buf[2 * KEY_DIM + c];
    if (tid < NV) {
        float bb = g_ba[(size_t)bs * 64 + tid];
        float aa = g_ba[(size_t)bs * 64 + NV + tid];
        float be = 1.f / (1.f + expf(-bb));
        float x = aa + dt_bias[tid];
        float sp = (x > 20.f) ? x : log1pf(expf(x));
        float g = -expf(A_log[tid]) * sp;
        g_ge[(size_t)bs * NV + tid] = expf(g);
        g_beta[(size_t)bs * NV + tid] = be;
    }
}

// ---------------- sequential delta-rule scan (double-buffered) -------------
__global__ void __launch_bounds__(256) scan_kernel() {
    const int bh = blockIdx.x;
    const int b = bh >> 5, h = bh & 31;
    const int hk = h >> 1;
    const int tid = threadIdx.x;
    const int warp = tid >> 5, lane = tid & 31;
    const int kg = lane & 3;
    const int col = blockIdx.y * 64 + warp * 8 + (lane >> 2);

    __shared__ __align__(16) float shk[2][128];
    __shared__ __align__(16) float shq[2][128];

    float st[32];
#pragma unroll
    for (int i = 0; i < 32; i++) st[i] = 0.f;

    int bs = b << 11;
    float pk;
    if (tid < 128) pk = g_kn[((size_t)bs * NK + hk) * DK + tid];
    else           pk = g_qn[((size_t)bs * NK + hk) * DK + (tid - 128)];
    float gv = g_ge[(size_t)bs * NV + h];
    float bv = g_beta[(size_t)bs * NV + h];
    float vv = g_v[((size_t)bs * NV + h) * DV + col];

    if (tid < 128) shk[0][tid] = pk;
    else           shq[0][tid - 128] = pk;
    __syncthreads();

    for (int s = 0; s < S_DIM; s++) {
        const int p = s & 1;
        float nk = 0.f, ng = 0.f, nb = 0.f, nv = 0.f;
        if (s + 1 < S_DIM) {
            int bs2 = (b << 11) + s + 1;
            if (tid < 128) nk = g_kn[((size_t)bs2 * NK + hk) * DK + tid];
            else           nk = g_qn[((size_t)bs2 * NK + hk) * DK + (tid - 128)];
            ng = g_ge[(size_t)bs2 * NV + h];
            nb = g_beta[(size_t)bs2 * NV + h];
            nv = g_v[((size_t)bs2 * NV + h) * DV + col];
        }

        const float4* k4 = (const float4*)shk[p];
        const float4* q4 = (const float4*)shq[p];

        float4 kv[8];
        float p0 = 0.f, p1 = 0.f, p2 = 0.f, p3 = 0.f;
#pragma unroll
        for (int j = 0; j < 8; j++) {
            kv[j] = k4[kg * 8 + j];
            p0 += kv[j].x * st[4 * j + 0];
            p1 += kv[j].y * st[4 * j + 1];
            p2 += kv[j].z * st[4 * j + 2];
            p3 += kv[j].w * st[4 * j + 3];
        }
        float part = (p0 + p1) + (p2 + p3);
        part += __shfl_xor_sync(0xffffffffu, part, 1);
        part += __shfl_xor_sync(0xffffffffu, part, 2);

        float delta = bv * (vv - gv * part);

        float o0 = 0.f, o1 = 0.f, o2 = 0.f, o3 = 0.f;
#pragma unroll
        for (int j = 0; j < 8; j++) {
            float4 qv = q4[kg * 8 + j];
            float s0 = st[4 * j + 0] * gv + kv[j].x * delta;
            float s1 = st[4 * j + 1] * gv + kv[j].y * delta;
            float s2 = st[4 * j + 2] * gv + kv[j].z * delta;
            float s3 = st[4 * j + 3] * gv + kv[j].w * delta;
            st[4 * j + 0] = s0; st[4 * j + 1] = s1;
            st[4 * j + 2] = s2; st[4 * j + 3] = s3;
            o0 += qv.x * s0; o1 += qv.y * s1;
            o2 += qv.z * s2; o3 += qv.w * s3;
        }
        float o = (o0 + o1) + (o2 + o3);
        o += __shfl_xor_sync(0xffffffffu, o, 1);
        o += __shfl_xor_sync(0xffffffffu, o, 2);

        if (kg == 0) {
            int bsc = (b << 11) + s;
            g_core[((size_t)bsc * NV + h) * DV + col] = o;
        }

        if (s + 1 < S_DIM) {
            if (tid < 128) shk[p ^ 1][tid] = nk;
            else           shq[p ^ 1][tid - 128] = nk;
        }
        __syncthreads();
        gv = ng; bv = nb; vv = nv;
    }
}

// ---------------- RMSNorm + silu(z) gate -> bf16 hi/lo directly ------------
__global__ void __launch_bounds__(256) rmsgate_kernel(const float* __restrict__ norm_w) {
    const int r = blockIdx.x;
    const int tid = threadIdx.x;
    const float* row = g_core + (size_t)r * VAL_DIM;
    __shared__ float red[8];
    float ss = 0.f;
    for (int i = tid; i < VAL_DIM; i += 256) {
        float x = row[i];
        ss += x * x;
    }
#pragma unroll
    for (int o = 16; o; o >>= 1) ss += __shfl_xor_sync(0xffffffffu, ss, o);
    if ((tid & 31) == 0) red[tid >> 5] = ss;
    __syncthreads();
    if (tid == 0) {
        float tot = 0.f;
#pragma unroll
        for (int i = 0; i < 8; i++) tot += red[i];
        red[0] = rsqrtf(tot / (float)VAL_DIM + EPS);
    }
    __syncthreads();
    const float scale = red[0];
    const float* zrow = g_qkvz + (size_t)r * QKVZ_DIM + (2 * KEY_DIM + VAL_DIM);
    __nv_bfloat16* hrow = g_chi + (size_t)r * VAL_DIM;
    __nv_bfloat16* lrow = g_clo + (size_t)r * VAL_DIM;
    for (int i = tid; i < VAL_DIM; i += 256) {
        float zv = zrow[i];
        float sil = zv / (1.f + __expf(-zv));
        float val = row[i] * scale * (1.f + norm_w[i]) * sil;
        __nv_bfloat16 hv = __float2bfloat16(val);
        hrow[i] = hv;
        lrow[i] = __float2bfloat16(val - __bfloat162float(hv));
    }
}

// ---------------- launch ----------------
extern "C" void kernel_launch(void* const* d_in, const int* in_sizes, int n_in,
                              void* d_out, int out_size) {
    const float* x       = (const float*)d_in[0];
    const float* W_qkvz  = (const float*)d_in[1];
    const float* W_ba    = (const float*)d_in[2];
    const float* conv_w  = (const float*)d_in[3];
    const float* dt_bias = (const float*)d_in[4];
    const float* A_log   = (const float*)d_in[5];
    const float* norm_w  = (const float*)d_in[6];
    const float* W_out   = (const float*)d_in[7];
    float* out = (float*)d_out;

    float *p_qkvz, *p_ba;
    cudaGetSymbolAddress((void**)&p_qkvz, g_qkvz);
    cudaGetSymbolAddress((void**)&p_ba, g_ba);
    __nv_bfloat16 *p_xhi, *p_xlo, *p_wqhi, *p_wqlo, *p_wohi, *p_wolo, *p_chi, *p_clo;
    cudaGetSymbolAddress((void**)&p_xhi, g_xhi);
    cudaGetSymbolAddress((void**)&p_xlo, g_xlo);
    cudaGetSymbolAddress((void**)&p_wqhi, g_wqhi);
    cudaGetSymbolAddress((void**)&p_wqlo, g_wqlo);
    cudaGetSymbolAddress((void**)&p_wohi, g_wohi);
    cudaGetSymbolAddress((void**)&p_wolo, g_wolo);
    cudaGetSymbolAddress((void**)&p_chi, g_chi);
    cudaGetSymbolAddress((void**)&p_clo, g_clo);

    cudaFuncSetAttribute(gemm_mma, cudaFuncAttributeMaxDynamicSharedMemorySize, MM_SMEM_TOTAL);

    {
        int n4 = (BS_TOT * H_SIZE) / 4;
        split_kernel<<<(n4 + 255) / 256, 256>>>((const float4*)x,
                                                (__nv_bfloat162*)p_xhi, (__nv_bfloat162*)p_xlo, n4);
    }
    {
        int n4 = (QKVZ_DIM * H_SIZE) / 4;
        split_kernel<<<(n4 + 255) / 256, 256>>>((const float4*)W_qkvz,
                                                (__nv_bfloat162*)p_wqhi, (__nv_bfloat162*)p_wqlo, n4);
    }
    {
        int n4 = (H_SIZE * VAL_DIM) / 4;
        split_kernel<<<(n4 + 255) / 256, 256>>>((const float4*)W_out,
                                                (__nv_bfloat162*)p_wohi, (__nv_bfloat162*)p_wolo, n4);
    }
    gemm_mma<<<dim3(QKVZ_DIM / MM_BN, BS_TOT / MM_BM), 256, MM_SMEM_TOTAL>>>(
        p_xhi, p_xlo, p_wqhi, p_wqlo, p_qkvz, BS_TOT, QKVZ_DIM, H_SIZE);
    zero_kernel<<<(BS_TOT * 64) / (256 * 4), 256>>>((float4*)p_ba);
    gemm_ba<<<dim3(1, BS_TOT / 128, H_SIZE / BA_KSLICE), 256>>>(x, W_ba, p_ba,
                                                                BS_TOT, 64, H_SIZE);
    conv_gate_kernel<<<BS_TOT, 256>>>(conv_w, dt_bias, A_log);
    scan_kernel<<<dim3(64, 2), 256>>>();
    rmsgate_kernel<<<BS_TOT, 256>>>(norm_w);
    gemm_mma<<<dim3(H_SIZE / MM_BN, BS_TOT / MM_BM), 256, MM_SMEM_TOTAL>>>(
        p_chi, p_clo, p_wohi, p_wolo, out, BS_TOT, H_SIZE, VAL_DIM);
}

// round 13
// speedup vs baseline: 1.1678x; 1.1340x over previous
#include <cuda_runtime.h>
#include <cuda_fp16.h>
#include <cuda_bf16.h>
#include <math.h>
#include <stdint.h>

// ---------------- problem dims ----------------
#define B_DIM 2
#define S_DIM 2048
#define H_SIZE 2048
#define NK 16
#define NV 32
#define DK 128
#define DV 128
#define KEY_DIM 2048
#define VAL_DIM 4096
#define QKVZ_DIM 12288
#define CONV_DIM 8192
#define BS_TOT (B_DIM * S_DIM)   // 4096
#define EPS 1e-6f

// ---------------- scratch ----------------
__device__ float g_qkvz[(size_t)BS_TOT * QKVZ_DIM];
__device__ float g_ba[(size_t)BS_TOT * 64];
__device__ float g_qn[(size_t)BS_TOT * KEY_DIM];
__device__ float g_kn[(size_t)BS_TOT * KEY_DIM];
__device__ float g_v[(size_t)BS_TOT * VAL_DIM];
__device__ float g_ge[(size_t)BS_TOT * NV];
__device__ float g_beta[(size_t)BS_TOT * NV];
__device__ float g_core[(size_t)BS_TOT * VAL_DIM];

__device__ __half g_xhi[(size_t)BS_TOT * H_SIZE];
__device__ __half g_xlo[(size_t)BS_TOT * H_SIZE];
__device__ __half g_wqhi[(size_t)QKVZ_DIM * H_SIZE];
__device__ __half g_wohi[(size_t)H_SIZE * VAL_DIM];
__device__ __half g_chi[(size_t)BS_TOT * VAL_DIM];
__device__ __half g_clo[(size_t)BS_TOT * VAL_DIM];

// ---------------- helpers ----------------
__device__ __forceinline__ uint32_t smem_u32(const void* p) {
    uint32_t a;
    asm("{ .reg .u64 t; cvta.to.shared.u64 t, %1; cvt.u32.u64 %0, t; }" : "=r"(a) : "l"(p));
    return a;
}
__device__ __forceinline__ void cp16(uint32_t dst, const void* src) {
    asm volatile("cp.async.cg.shared.global [%0], [%1], 16;" :: "r"(dst), "l"(src) : "memory");
}
template <int N> __device__ __forceinline__ void cp_wait() {
    asm volatile("cp.async.wait_group %0;" :: "n"(N) : "memory");
}
__device__ __forceinline__ void ldmatrix4(uint32_t* r, uint32_t addr) {
    asm volatile("ldmatrix.sync.aligned.m8n8.x4.shared.b16 {%0,%1,%2,%3}, [%4];"
                 : "=r"(r[0]), "=r"(r[1]), "=r"(r[2]), "=r"(r[3]) : "r"(addr));
}
__device__ __forceinline__ void mma16816h(float* c, const uint32_t* a, uint32_t b0, uint32_t b1) {
    asm volatile(
        "mma.sync.aligned.m16n8k16.row.col.f32.f16.f16.f32 "
        "{%0,%1,%2,%3}, {%4,%5,%6,%7}, {%8,%9}, {%0,%1,%2,%3};"
        : "+f"(c[0]), "+f"(c[1]), "+f"(c[2]), "+f"(c[3])
        : "r"(a[0]), "r"(a[1]), "r"(a[2]), "r"(a[3]), "r"(b0), "r"(b1));
}

// ---------------- fp32 -> fp16 hi/lo split (hi+lo) ----------------
__global__ void __launch_bounds__(256) split2_kernel(const float4* __restrict__ in,
                                                     __half2* __restrict__ hi,
                                                     __half2* __restrict__ lo,
                                                     int n4) {
    int i = blockIdx.x * 256 + threadIdx.x;
    if (i >= n4) return;
    float4 v = in[i];
    __half hx = __float2half(v.x), hy = __float2half(v.y);
    __half hz = __float2half(v.z), hw = __float2half(v.w);
    __half lx = __float2half(v.x - __half2float(hx));
    __half ly = __float2half(v.y - __half2float(hy));
    __half lz = __float2half(v.z - __half2float(hz));
    __half lw = __float2half(v.w - __half2float(hw));
    hi[2 * i] = __halves2half2(hx, hy);
    hi[2 * i + 1] = __halves2half2(hz, hw);
    lo[2 * i] = __halves2half2(lx, ly);
    lo[2 * i + 1] = __halves2half2(lz, lw);
}

// ---------------- fp32 -> fp16 hi only (weights) ----------------
__global__ void __launch_bounds__(256) split1_kernel(const float4* __restrict__ in,
                                                     __half2* __restrict__ hi,
                                                     int n4) {
    int i = blockIdx.x * 256 + threadIdx.x;
    if (i >= n4) return;
    float4 v = in[i];
    hi[2 * i] = __halves2half2(__float2half(v.x), __float2half(v.y));
    hi[2 * i + 1] = __halves2half2(__float2half(v.z), __float2half(v.w));
}

// ---------------- fused 2-pass fp16 mma.sync GEMM, 2 CTAs/SM ---------------
// C = (Ahi + Alo) @ Bhi^T. Tile 128x128x64, warp 64x32, 8 warps (2M x 4N),
// 2-stage double buffer (48KB/stage, 96KB/CTA), 2 CTAs/SM.
#define MM_BM 128
#define MM_BN 128
#define MM_BK 64
#define MM_TILE_BYTES 16384
#define MM_STAGE_BYTES (3 * MM_TILE_BYTES)   // [Ahi][Alo][Bhi]
#define MM_SMEM_TOTAL (2 * MM_STAGE_BYTES)   // 98304

__global__ void __launch_bounds__(256, 2)
gemm_mma(const __half* __restrict__ Ahi, const __half* __restrict__ Alo,
         const __half* __restrict__ Bhi,
         float* __restrict__ C, int M, int N, int K) {
    extern __shared__ char smem[];
    const uint32_t sbase = smem_u32(smem);
    const int tid = threadIdx.x, wid = tid >> 5, lane = tid & 31;
    const int wm = wid & 1;            // 0..1 -> 64 rows
    const int wn = wid >> 1;           // 0..3 -> 32 cols

    const int m0 = blockIdx.y * MM_BM;
    const int n0 = blockIdx.x * MM_BN;
    const int KT = K / MM_BK;

    const int a_lr = lane & 15;
    const uint32_t a_colb = (uint32_t)((lane >> 4) * 16);
    const int b_l = lane & 7, b_q = lane >> 3;
    const uint32_t b_colb = (uint32_t)((b_q & 1) * 16);

    uint32_t arb[4], asw[4], brb[2], bsw[2];
#pragma unroll
    for (int i = 0; i < 4; i++) {
        uint32_t row = (uint32_t)(wm * 64 + a_lr + i * 16);
        arb[i] = row * 128;
        asw[i] = (arb[i] >> 3) & 0x70;
    }
#pragma unroll
    for (int j = 0; j < 2; j++) {
        uint32_t row = (uint32_t)(wn * 32 + (b_q >> 1) * 8 + b_l + j * 16);
        brb[j] = row * 128;
        bsw[j] = (brb[j] >> 3) & 0x70;
    }

    float acc[4][4][4];
#pragma unroll
    for (int i = 0; i < 4; i++)
#pragma unroll
        for (int j = 0; j < 4; j++)
#pragma unroll
            for (int q = 0; q < 4; q++) acc[i][j][q] = 0.f;

    auto load_tile = [&](int kt, int stage) {
        const __half* Aph = Ahi + (size_t)m0 * K + kt * MM_BK;
        const __half* Apl = Alo + (size_t)m0 * K + kt * MM_BK;
        const __half* Bph = Bhi + (size_t)n0 * K + kt * MM_BK;
        uint32_t sS = sbase + stage * MM_STAGE_BYTES;
#pragma unroll
        for (int i = 0; i < 4; i++) {
            int idx = tid + i * 256;               // 1024 chunks per tile
            int row = idx >> 3, u = idx & 7;
            uint32_t off = row * 128 + u * 16;
            off ^= (off >> 3) & 0x70;
            size_t goff = (size_t)row * K + u * 8;
            cp16(sS + off, Aph + goff);
            cp16(sS + MM_TILE_BYTES + off, Apl + goff);
            cp16(sS + 2 * MM_TILE_BYTES + off, Bph + goff);
        }
        asm volatile("cp.async.commit_group;" ::: "memory");
    };

    load_tile(0, 0);
    for (int t = 0; t < KT; t++) {
        cp_wait<0>();
        __syncthreads();
        if (t + 1 < KT) load_tile(t + 1, (t + 1) & 1);

        uint32_t sS = sbase + (t & 1) * MM_STAGE_BYTES;
        uint32_t sB = sS + 2 * MM_TILE_BYTES;
#pragma unroll
        for (int kk = 0; kk < 4; kk++) {
            uint32_t kc = (uint32_t)(kk * 32);
            uint32_t bh[2][4];
#pragma unroll
            for (int j = 0; j < 2; j++)
                ldmatrix4(bh[j], sB + brb[j] + ((kc + b_colb) ^ bsw[j]));
#pragma unroll
            for (int ih = 0; ih < 2; ih++) {
                uint32_t ah[2][4], al[2][4];
#pragma unroll
                for (int i2 = 0; i2 < 2; i2++) {
                    int i = ih * 2 + i2;
                    uint32_t ad = sS + arb[i] + ((kc + a_colb) ^ asw[i]);
                    ldmatrix4(ah[i2], ad);
                    ldmatrix4(al[i2], ad + MM_TILE_BYTES);
                }
                // sweep 1: hi*hi (8 independent MMAs)
#pragma unroll
                for (int i2 = 0; i2 < 2; i2++)
#pragma unroll
                    for (int j = 0; j < 2; j++) {
                        int i = ih * 2 + i2;
                        mma16816h(acc[i][2 * j],     ah[i2], bh[j][0], bh[j][1]);
                        mma16816h(acc[i][2 * j + 1], ah[i2], bh[j][2], bh[j][3]);
                    }
                // sweep 2: lo*hi
#pragma unroll
                for (int i2 = 0; i2 < 2; i2++)
#pragma unroll
                    for (int j = 0; j < 2; j++) {
                        int i = ih * 2 + i2;
                        mma16816h(acc[i][2 * j],     al[i2], bh[j][0], bh[j][1]);
                        mma16816h(acc[i][2 * j + 1], al[i2], bh[j][2], bh[j][3]);
                    }
            }
        }
    }

    const int row0 = m0 + wm * 64 + (lane >> 2);
    const int col0 = n0 + wn * 32 + (lane & 3) * 2;
#pragma unroll
    for (int i = 0; i < 4; i++)
#pragma unroll
        for (int j = 0; j < 4; j++) {
            int r = row0 + i * 16;
            int c = col0 + j * 8;
            *(float2*)&C[(size_t)r * N + c] = make_float2(acc[i][j][0], acc[i][j][1]);
            *(float2*)&C[(size_t)(r + 8) * N + c] = make_float2(acc[i][j][2], acc[i][j][3]);
        }
}

// ---------------- zero kernel ----------------
__global__ void __launch_bounds__(256) zero_kernel(float4* p) {
    p[blockIdx.x * 256 + threadIdx.x] = make_float4(0.f, 0.f, 0.f, 0.f);
}

// ---------------- split-K SIMT GEMM for ba (N=64) ----------------
#define BA_KSLICE 256
__global__ void __launch_bounds__(256) gemm_ba(const float* __restrict__ A,
                                               const float* __restrict__ B,
                                               float* __restrict__ C,
                                               int M, int N, int K) {
    __shared__ float As[8][128];
    __shared__ float Bs[8][64];
    const int tid = threadIdx.x;
    const int m0 = blockIdx.y * 128;
    const int k_base = blockIdx.z * BA_KSLICE;
    const int lr = tid >> 1;
    const int lk = (tid & 1) * 4;
    const int tx = tid & 15;
    const int ty = tid >> 4;
    const float* Aptr = A + (size_t)(m0 + lr) * K + k_base + lk;
    const float* Bptr = B + (size_t)lr * K + k_base + lk;
    const bool bvalid = lr < 64;

    float acc[8][4];
#pragma unroll
    for (int i = 0; i < 8; i++)
#pragma unroll
        for (int j = 0; j < 4; j++) acc[i][j] = 0.f;

    for (int k0 = 0; k0 < BA_KSLICE; k0 += 8) {
        float4 av = *(const float4*)Aptr;
        float4 bv = bvalid ? *(const float4*)Bptr : make_float4(0.f, 0.f, 0.f, 0.f);
        Aptr += 8; Bptr += 8;
        __syncthreads();
        As[lk + 0][lr] = av.x; As[lk + 1][lr] = av.y;
        As[lk + 2][lr] = av.z; As[lk + 3][lr] = av.w;
        if (bvalid) {
            Bs[lk + 0][lr] = bv.x; Bs[lk + 1][lr] = bv.y;
            Bs[lk + 2][lr] = bv.z; Bs[lk + 3][lr] = bv.w;
        }
        __syncthreads();
#pragma unroll
        for (int kk = 0; kk < 8; kk++) {
            float a[8], b[4];
            float4 a0 = *(const float4*)&As[kk][ty * 4];
            float4 a1 = *(const float4*)&As[kk][ty * 4 + 64];
            a[0]=a0.x; a[1]=a0.y; a[2]=a0.z; a[3]=a0.w;
            a[4]=a1.x; a[5]=a1.y; a[6]=a1.z; a[7]=a1.w;
            float4 bcol = *(const float4*)&Bs[kk][tx * 4];
            b[0]=bcol.x; b[1]=bcol.y; b[2]=bcol.z; b[3]=bcol.w;
#pragma unroll
            for (int i = 0; i < 8; i++)
#pragma unroll
                for (int j = 0; j < 4; j++) acc[i][j] += a[i] * b[j];
        }
    }
#pragma unroll
    for (int i = 0; i < 8; i++) {
        int m = m0 + ty * 4 + (i & 3) + ((i >> 2) * 64);
#pragma unroll
        for (int j = 0; j < 4; j++) {
            int n = tx * 4 + j;
            atomicAdd(&C[(size_t)m * N + n], acc[i][j]);
        }
    }
}

// ---------------- conv + silu + l2norm + gate precompute ----------------
__global__ void __launch_bounds__(256) conv_gate_kernel(
    const float* __restrict__ conv_w, const float* __restrict__ dt_bias,
    const float* __restrict__ A_log) {
    const int bs = blockIdx.x;
    const int s  = bs & (S_DIM - 1);
    const int tid = threadIdx.x;
    __shared__ float buf[CONV_DIM];
    __shared__ float sc[32];
    const float* base = g_qkvz + (size_t)bs * QKVZ_DIM;
    for (int c = tid; c < CONV_DIM; c += 256) {
        float4 w = *(const float4*)&conv_w[c * 4];
        float acc = base[c] * w.w;
        if (s >= 1) acc += g_qkvz[(size_t)(bs - 1) * QKVZ_DIM + c] * w.z;
        if (s >= 2) acc += g_qkvz[(size_t)(bs - 2) * QKVZ_DIM + c] * w.y;
        if (s >= 3) acc += g_qkvz[(size_t)(bs - 3) * QKVZ_DIM + c] * w.x;
        float sg = 1.f / (1.f + __expf(-acc));
        buf[c] = acc * sg;
    }
    __syncthreads();
    const int warp = tid >> 5, lane = tid & 31;
    for (int hh = warp * 4; hh < warp * 4 + 4; hh++) {
        float sum = 0.f;
#pragma unroll
        for (int i = 0; i < 4; i++) {
            float x = buf[hh * 128 + lane + i * 32];
            sum += x * x;
        }
#pragma unroll
        for (int o = 16; o; o >>= 1) sum += __shfl_xor_sync(0xffffffffu, sum, o);
        if (lane == 0) sc[hh] = rsqrtf(sum + EPS);
    }
    __syncthreads();
    float* qnrow = g_qn + (size_t)bs * KEY_DIM;
    float* knrow = g_kn + (size_t)bs * KEY_DIM;
    float* vrow  = g_v  + (size_t)bs * VAL_DIM;
    for (int c = tid; c < KEY_DIM; c += 256) qnrow[c] = buf[c] * sc[c >> 7];
    for (int c = tid; c < KEY_DIM; c += 256) knrow[c] = buf[KEY_DIM + c] * sc[16 + (c >> 7)];
    for (int c = tid; c < VAL_DIM; c += 256) vrow[c] = buf[2 * KEY_DIM + c];
    if (tid < NV) {
        float bb = g_ba[(size_t)bs * 64 + tid];
        float aa = g_ba[(size_t)bs * 64 + NV + tid];
        float be = 1.f / (1.f + expf(-bb));
        float x = aa + dt_bias[tid];
        float sp = (x > 20.f) ? x : log1pf(expf(x));
        float g = -expf(A_log[tid]) * sp;
        g_ge[(size_t)bs * NV + tid] = expf(g);
        g_beta[(size_t)bs * NV + tid] = be;
    }
}

// ---------------- sequential delta-rule scan (double-buffered) -------------
__global__ void __launch_bounds__(256) scan_kernel() {
    const int bh = blockIdx.x;
    const int b = bh >> 5, h = bh & 31;
    const int hk = h >> 1;
    const int tid = threadIdx.x;
    const int warp = tid >> 5, lane = tid & 31;
    const int kg = lane & 3;
    const int col = blockIdx.y * 64 + warp * 8 + (lane >> 2);

    __shared__ __align__(16) float shk[2][128];
    __shared__ __align__(16) float shq[2][128];

    float st[32];
#pragma unroll
    for (int i = 0; i < 32; i++) st[i] = 0.f;

    int bs = b << 11;
    float pk;
    if (tid < 128) pk = g_kn[((size_t)bs * NK + hk) * DK + tid];
    else           pk = g_qn[((size_t)bs * NK + hk) * DK + (tid - 128)];
    float gv = g_ge[(size_t)bs * NV + h];
    float bv = g_beta[(size_t)bs * NV + h];
    float vv = g_v[((size_t)bs * NV + h) * DV + col];

    if (tid < 128) shk[0][tid] = pk;
    else           shq[0][tid - 128] = pk;
    __syncthreads();

    for (int s = 0; s < S_DIM; s++) {
        const int p = s & 1;
        float nk = 0.f, ng = 0.f, nb = 0.f, nv = 0.f;
        if (s + 1 < S_DIM) {
            int bs2 = (b << 11) + s + 1;
            if (tid < 128) nk = g_kn[((size_t)bs2 * NK + hk) * DK + tid];
            else           nk = g_qn[((size_t)bs2 * NK + hk) * DK + (tid - 128)];
            ng = g_ge[(size_t)bs2 * NV + h];
            nb = g_beta[(size_t)bs2 * NV + h];
            nv = g_v[((size_t)bs2 * NV + h) * DV + col];
        }

        const float4* k4 = (const float4*)shk[p];
        const float4* q4 = (const float4*)shq[p];

        float4 kv[8];
        float p0 = 0.f, p1 = 0.f, p2 = 0.f, p3 = 0.f;
#pragma unroll
        for (int j = 0; j < 8; j++) {
            kv[j] = k4[kg * 8 + j];
            p0 += kv[j].x * st[4 * j + 0];
            p1 += kv[j].y * st[4 * j + 1];
            p2 += kv[j].z * st[4 * j + 2];
            p3 += kv[j].w * st[4 * j + 3];
        }
        float part = (p0 + p1) + (p2 + p3);
        part += __shfl_xor_sync(0xffffffffu, part, 1);
        part += __shfl_xor_sync(0xffffffffu, part, 2);

        float delta = bv * (vv - gv * part);

        float o0 = 0.f, o1 = 0.f, o2 = 0.f, o3 = 0.f;
#pragma unroll
        for (int j = 0; j < 8; j++) {
            float4 qv = q4[kg * 8 + j];
            float s0 = st[4 * j + 0] * gv + kv[j].x * delta;
            float s1 = st[4 * j + 1] * gv + kv[j].y * delta;
            float s2 = st[4 * j + 2] * gv + kv[j].z * delta;
            float s3 = st[4 * j + 3] * gv + kv[j].w * delta;
            st[4 * j + 0] = s0; st[4 * j + 1] = s1;
            st[4 * j + 2] = s2; st[4 * j + 3] = s3;
            o0 += qv.x * s0; o1 += qv.y * s1;
            o2 += qv.z * s2; o3 += qv.w * s3;
        }
        float o = (o0 + o1) + (o2 + o3);
        o += __shfl_xor_sync(0xffffffffu, o, 1);
        o += __shfl_xor_sync(0xffffffffu, o, 2);

        if (kg == 0) {
            int bsc = (b << 11) + s;
            g_core[((size_t)bsc * NV + h) * DV + col] = o;
        }

        if (s + 1 < S_DIM) {
            if (tid < 128) shk[p ^ 1][tid] = nk;
            else           shq[p ^ 1][tid - 128] = nk;
        }
        __syncthreads();
        gv = ng; bv = nb; vv = nv;
    }
}

// ---------------- RMSNorm + silu(z) gate -> fp16 hi/lo directly ------------
__global__ void __launch_bounds__(256) rmsgate_kernel(const float* __restrict__ norm_w) {
    const int r = blockIdx.x;
    const int tid = threadIdx.x;
    const float* row = g_core + (size_t)r * VAL_DIM;
    __shared__ float red[8];
    float ss = 0.f;
    for (int i = tid; i < VAL_DIM; i += 256) {
        float x = row[i];
        ss += x * x;
    }
#pragma unroll
    for (int o = 16; o; o >>= 1) ss += __shfl_xor_sync(0xffffffffu, ss, o);
    if ((tid & 31) == 0) red[tid >> 5] = ss;
    __syncthreads();
    if (tid == 0) {
        float tot = 0.f;
#pragma unroll
        for (int i = 0; i < 8; i++) tot += red[i];
        red[0] = rsqrtf(tot / (float)VAL_DIM + EPS);
    }
    __syncthreads();
    const float scale = red[0];
    const float* zrow = g_qkvz + (size_t)r * QKVZ_DIM + (2 * KEY_DIM + VAL_DIM);
    __half* hrow = g_chi + (size_t)r * VAL_DIM;
    __half* lrow = g_clo + (size_t)r * VAL_DIM;
    for (int i = tid; i < VAL_DIM; i += 256) {
        float zv = zrow[i];
        float sil = zv / (1.f + __expf(-zv));
        float val = row[i] * scale * (1.f + norm_w[i]) * sil;
        __half hv = __float2half(val);
        hrow[i] = hv;
        lrow[i] = __float2half(val - __half2float(hv));
    }
}

// ---------------- launch ----------------
extern "C" void kernel_launch(void* const* d_in, const int* in_sizes, int n_in,
                              void* d_out, int out_size) {
    const float* x       = (const float*)d_in[0];
    const float* W_qkvz  = (const float*)d_in[1];
    const float* W_ba    = (const float*)d_in[2];
    const float* conv_w  = (const float*)d_in[3];
    const float* dt_bias = (const float*)d_in[4];
    const float* A_log   = (const float*)d_in[5];
    const float* norm_w  = (const float*)d_in[6];
    const float* W_out   = (const float*)d_in[7];
    float* out = (float*)d_out;

    float *p_qkvz, *p_ba;
    cudaGetSymbolAddress((void**)&p_qkvz, g_qkvz);
    cudaGetSymbolAddress((void**)&p_ba, g_ba);
    __half *p_xhi, *p_xlo, *p_wqhi, *p_wohi, *p_chi, *p_clo;
    cudaGetSymbolAddress((void**)&p_xhi, g_xhi);
    cudaGetSymbolAddress((void**)&p_xlo, g_xlo);
    cudaGetSymbolAddress((void**)&p_wqhi, g_wqhi);
    cudaGetSymbolAddress((void**)&p_wohi, g_wohi);
    cudaGetSymbolAddress((void**)&p_chi, g_chi);
    cudaGetSymbolAddress((void**)&p_clo, g_clo);

    cudaFuncSetAttribute(gemm_mma, cudaFuncAttributeMaxDynamicSharedMemorySize, MM_SMEM_TOTAL);

    {
        int n4 = (BS_TOT * H_SIZE) / 4;
        split2_kernel<<<(n4 + 255) / 256, 256>>>((const float4*)x,
                                                 (__half2*)p_xhi, (__half2*)p_xlo, n4);
    }
    {
        int n4 = (QKVZ_DIM * H_SIZE) / 4;
        split1_kernel<<<(n4 + 255) / 256, 256>>>((const float4*)W_qkvz,
                                                 (__half2*)p_wqhi, n4);
    }
    {
        int n4 = (H_SIZE * VAL_DIM) / 4;
        split1_kernel<<<(n4 + 255) / 256, 256>>>((const float4*)W_out,
                                                 (__half2*)p_wohi, n4);
    }
    // 1) qkvz = x @ W_qkvz^T  (fp16 2-pass)
    gemm_mma<<<dim3(QKVZ_DIM / MM_BN, BS_TOT / MM_BM), 256, MM_SMEM_TOTAL>>>(
        p_xhi, p_xlo, p_wqhi, p_qkvz, BS_TOT, QKVZ_DIM, H_SIZE);
    // 2) ba = x @ W_ba^T (split-K + atomics)
    zero_kernel<<<(BS_TOT * 64) / (256 * 4), 256>>>((float4*)p_ba);
    gemm_ba<<<dim3(1, BS_TOT / 128, H_SIZE / BA_KSLICE), 256>>>(x, W_ba, p_ba,
                                                                BS_TOT, 64, H_SIZE);
    conv_gate_kernel<<<BS_TOT, 256>>>(conv_w, dt_bias, A_log);
    scan_kernel<<<dim3(64, 2), 256>>>();
    rmsgate_kernel<<<BS_TOT, 256>>>(norm_w);
    // 6) out = core @ W_out^T (fp16 2-pass)
    gemm_mma<<<dim3(H_SIZE / MM_BN, BS_TOT / MM_BM), 256, MM_SMEM_TOTAL>>>(
        p_chi, p_clo, p_wohi, out, BS_TOT, H_SIZE, VAL_DIM);
}